// round 7
// baseline (speedup 1.0000x reference)
#include <cuda_runtime.h>
#include <cuda_bf16.h>
#include <cstdint>

#define BB   2
#define SS   2048
#define DD   1024
#define DD2  512
#define HH   16
#define HDIM 64
#define MTOT (BB*SS)          // 4096
#define SCALE_ATTN 0.125f

// ---------------- scratch (device globals; no allocation allowed) ----------
// pre-split inputs: 3 segments (query,key,value), each MTOT x DD2 pairs
__device__ unsigned g_Xh[(size_t)3*MTOT*DD2];
__device__ unsigned g_Xl[(size_t)3*MTOT*DD2];
// pre-split weights: 4 segments (Wq,Wk,Wv,Wo), each DD x DD2 pairs
__device__ unsigned g_Wh[(size_t)4*DD*DD2];
__device__ unsigned g_Wl[(size_t)4*DD*DD2];
// projected Q,K (dim-pair packed, Q pre-scaled)
__device__ unsigned g_Qh[(size_t)MTOT*DD2];
__device__ unsigned g_Ql[(size_t)MTOT*DD2];
__device__ unsigned g_Kh[(size_t)MTOT*DD2];
__device__ unsigned g_Kl[(size_t)MTOT*DD2];
// V key-pair packed: (sp, d) = pack(V[2sp][d], V[2sp+1][d])
__device__ unsigned g_VkPh[(size_t)(MTOT/2)*DD];
__device__ unsigned g_VkPl[(size_t)(MTOT/2)*DD];
// attention output, pre-split for the O-projection
__device__ unsigned g_AOh[(size_t)MTOT*DD2];
__device__ unsigned g_AOl[(size_t)MTOT*DD2];
__device__ unsigned g_packed[MTOT];

// ---------------- id packing ----------------------------------------------
#define MF   0x1Fu
#define ME   (0x3Fu<<5)
#define MT   (0x7Fu<<11)
#define MTT  (0x7u<<18)
#define MR   (0x7u<<21)
#define EDNZ (1u<<24)
#define PADB (1u<<25)

__global__ void pack_ids_kernel(const int* __restrict__ f, const int* __restrict__ e,
                                const int* __restrict__ t, const int* __restrict__ tt,
                                const int* __restrict__ ed, const int* __restrict__ r,
                                int n)
{
    int i = blockIdx.x * blockDim.x + threadIdx.x;
    if (i < n) {
        unsigned p = ((unsigned)f[i] & 31u)
                   | (((unsigned)e[i] & 63u) << 5)
                   | (((unsigned)t[i] & 127u) << 11)
                   | (((unsigned)tt[i] & 7u) << 18)
                   | (((unsigned)r[i] & 7u) << 21)
                   | ((ed[i] != 0) ? EDNZ : 0u)
                   | ((f[i] == 0) ? PADB : 0u);
        g_packed[i] = p;
    }
}

// ---------------- bf16 split helpers ---------------------------------------
__device__ __forceinline__ void split2(float a, float b, unsigned& h, unsigned& l) {
    __nv_bfloat162 hh = __floats2bfloat162_rn(a, b);
    float ra = a - __bfloat162float(hh.x);
    float rb = b - __bfloat162float(hh.y);
    __nv_bfloat162 ll = __floats2bfloat162_rn(ra, rb);
    h = *(unsigned*)&hh;
    l = *(unsigned*)&ll;
}

// dst: tag 0 = g_Xh/g_Xl, tag 1 = g_Wh/g_Wl; off = pair offset of segment
__global__ void split_src_kernel(const float* __restrict__ src, int tag,
                                 size_t off, int npairs)
{
    unsigned* h = (tag == 0) ? g_Xh : g_Wh;
    unsigned* l = (tag == 0) ? g_Xl : g_Wl;
    int i = blockIdx.x * blockDim.x + threadIdx.x;
    if (i < npairs) {
        float2 v = ((const float2*)src)[i];
        unsigned hh, ll;
        split2(v.x, v.y, hh, ll);
        h[off + i] = hh;
        l[off + i] = ll;
    }
}

__device__ __forceinline__ void mma_bf16(float c[4], const unsigned a[4],
                                         unsigned b0, unsigned b1) {
    asm volatile(
        "mma.sync.aligned.m16n8k16.row.col.f32.bf16.bf16.f32 "
        "{%0,%1,%2,%3},{%4,%5,%6,%7},{%8,%9},{%0,%1,%2,%3};"
        : "+f"(c[0]), "+f"(c[1]), "+f"(c[2]), "+f"(c[3])
        : "r"(a[0]), "r"(a[1]), "r"(a[2]), "r"(a[3]), "r"(b0), "r"(b1));
}

#define LDMX4(r0, r1, r2, r3, addr) \
    asm volatile("ldmatrix.sync.aligned.m8n8.x4.shared.b16 {%0,%1,%2,%3}, [%4];" \
                 : "=r"(r0), "=r"(r1), "=r"(r2), "=r"(r3) : "r"(addr))

__device__ __forceinline__ unsigned smem_u32(const void* p) {
    return (unsigned)__cvta_generic_to_shared(p);
}

// ---------------- GEMM (pre-split bf16, ldmatrix): Y = X W^T + bias --------
// block 128x128, BK=32 (16 pairs), 8 warps each 32(M)x64(N), 3-product bf16x2.
// final_=0: grid.z selects query/key/value -> Q/K/V epilogues.
// final_=1: X=g_AO (split), W=Wo, float output to Yext.
__global__ __launch_bounds__(256, 1)
void gemm_pre(const float* __restrict__ bias0, const float* __restrict__ bias1,
              const float* __restrict__ bias2, float* __restrict__ Yext, int final_)
{
    const int z = final_ ? 3 : blockIdx.z;
    const unsigned* Xh = final_ ? g_AOh : g_Xh + (size_t)z * MTOT * DD2;
    const unsigned* Xl = final_ ? g_AOl : g_Xl + (size_t)z * MTOT * DD2;
    const unsigned* Wh = g_Wh + (size_t)z * DD * DD2;
    const unsigned* Wl = g_Wl + (size_t)z * DD * DD2;
    const float* bias = final_ ? bias0 : (z == 0 ? bias0 : (z == 1 ? bias1 : bias2));
    const float out_scale = (!final_ && z == 0) ? SCALE_ATTN : 1.f;

    __shared__ unsigned XsH[128][20], XsL[128][20];
    __shared__ unsigned WsH[128][20], WsL[128][20];

    const int t = threadIdx.x;
    const int m_blk = blockIdx.y * 128;
    const int n_blk = blockIdx.x * 128;
    const int w = t >> 5, lane = t & 31;
    const int g = lane >> 2, tig = lane & 3;
    const int wm = w & 3, wn = w >> 2;

    // copy map: idx = i*256 + t; row = idx>>2 (0..127), c4 = idx&3 (uint4 col)
    int crow[2], cc4[2];
#pragma unroll
    for (int i = 0; i < 2; i++) { int idx = i * 256 + t; crow[i] = idx >> 2; cc4[i] = idx & 3; }

    uint4 xh[2], xl[2], wh[2], wl[2];
#pragma unroll
    for (int i = 0; i < 2; i++) {
        xh[i] = *(const uint4*)&Xh[(size_t)(m_blk + crow[i]) * DD2 + cc4[i] * 4];
        xl[i] = *(const uint4*)&Xl[(size_t)(m_blk + crow[i]) * DD2 + cc4[i] * 4];
        wh[i] = *(const uint4*)&Wh[(size_t)(n_blk + crow[i]) * DD2 + cc4[i] * 4];
        wl[i] = *(const uint4*)&Wl[(size_t)(n_blk + crow[i]) * DD2 + cc4[i] * 4];
    }

    // ldmatrix per-lane base addresses (bytes)
    const int rowA = lane & 15, colA = (lane >> 4) * 4;
    const int rowBo = (lane & 7) + ((lane >> 4) << 3), colB = ((lane >> 3) & 1) * 4;
    unsigned aH[2], aL[2], bH[4], bL[4];
#pragma unroll
    for (int mt = 0; mt < 2; mt++) {
        const int r = wm * 32 + mt * 16 + rowA;
        aH[mt] = smem_u32(&XsH[0][0]) + (r * 20 + colA) * 4;
        aL[mt] = smem_u32(&XsL[0][0]) + (r * 20 + colA) * 4;
    }
#pragma unroll
    for (int ntp = 0; ntp < 4; ntp++) {
        const int r = wn * 64 + ntp * 16 + rowBo;
        bH[ntp] = smem_u32(&WsH[0][0]) + (r * 20 + colB) * 4;
        bL[ntp] = smem_u32(&WsL[0][0]) + (r * 20 + colB) * 4;
    }

    float acc[2][8][4];
#pragma unroll
    for (int mt = 0; mt < 2; mt++)
#pragma unroll
        for (int nt = 0; nt < 8; nt++)
#pragma unroll
            for (int i = 0; i < 4; i++) acc[mt][nt][i] = 0.f;

    for (int kt = 0; kt < 32; kt++) {
#pragma unroll
        for (int i = 0; i < 2; i++) {
            *(uint4*)&XsH[crow[i]][cc4[i] * 4] = xh[i];
            *(uint4*)&XsL[crow[i]][cc4[i] * 4] = xl[i];
            *(uint4*)&WsH[crow[i]][cc4[i] * 4] = wh[i];
            *(uint4*)&WsL[crow[i]][cc4[i] * 4] = wl[i];
        }
        __syncthreads();
        if (kt < 31) {
            const int ko = (kt + 1) * 16;
#pragma unroll
            for (int i = 0; i < 2; i++) {
                xh[i] = *(const uint4*)&Xh[(size_t)(m_blk + crow[i]) * DD2 + ko + cc4[i] * 4];
                xl[i] = *(const uint4*)&Xl[(size_t)(m_blk + crow[i]) * DD2 + ko + cc4[i] * 4];
                wh[i] = *(const uint4*)&Wh[(size_t)(n_blk + crow[i]) * DD2 + ko + cc4[i] * 4];
                wl[i] = *(const uint4*)&Wl[(size_t)(n_blk + crow[i]) * DD2 + ko + cc4[i] * 4];
            }
        }
#pragma unroll
        for (int ks = 0; ks < 2; ks++) {
            const int kb = ks * 32;   // byte offset: 8 pairs
            unsigned ah[2][4], al[2][4];
#pragma unroll
            for (int mt = 0; mt < 2; mt++) {
                LDMX4(ah[mt][0], ah[mt][1], ah[mt][2], ah[mt][3], aH[mt] + kb);
                LDMX4(al[mt][0], al[mt][1], al[mt][2], al[mt][3], aL[mt] + kb);
            }
#pragma unroll
            for (int ntp = 0; ntp < 4; ntp++) {
                unsigned h0E, h1E, h0O, h1O, l0E, l1E, l0O, l1O;
                LDMX4(h0E, h1E, h0O, h1O, bH[ntp] + kb);
                LDMX4(l0E, l1E, l0O, l1O, bL[ntp] + kb);
#pragma unroll
                for (int mt = 0; mt < 2; mt++) {
                    mma_bf16(acc[mt][2 * ntp], ah[mt], h0E, h1E);
                    mma_bf16(acc[mt][2 * ntp], al[mt], h0E, h1E);
                    mma_bf16(acc[mt][2 * ntp], ah[mt], l0E, l1E);
                    mma_bf16(acc[mt][2 * ntp + 1], ah[mt], h0O, h1O);
                    mma_bf16(acc[mt][2 * ntp + 1], al[mt], h0O, h1O);
                    mma_bf16(acc[mt][2 * ntp + 1], ah[mt], l0O, l1O);
                }
            }
        }
        __syncthreads();
    }

    // ---------------- epilogue ----------------
    unsigned* Yh = (z == 0) ? g_Qh : g_Kh;
    unsigned* Yl = (z == 0) ? g_Ql : g_Kl;

#pragma unroll
    for (int mt = 0; mt < 2; mt++) {
        const int row0 = m_blk + wm * 32 + mt * 16 + g;
#pragma unroll
        for (int nt = 0; nt < 8; nt++) {
            const int col = n_blk + wn * 64 + nt * 8 + tig * 2;
            const float b0 = bias[col], b1 = bias[col + 1];
            float v0 = (acc[mt][nt][0] + b0) * out_scale;
            float v1 = (acc[mt][nt][1] + b1) * out_scale;
            float v2 = (acc[mt][nt][2] + b0) * out_scale;
            float v3 = (acc[mt][nt][3] + b1) * out_scale;

            if (final_) {
                float2 o0, o1;
                o0.x = v0; o0.y = v1; o1.x = v2; o1.y = v3;
                *(float2*)(Yext + (size_t)row0 * DD + col)       = o0;
                *(float2*)(Yext + (size_t)(row0 + 8) * DD + col) = o1;
            } else if (z == 2) {
                // key-pair repack for V
                float p0 = __shfl_xor_sync(0xffffffffu, v0, 4);
                float p1 = __shfl_xor_sync(0xffffffffu, v1, 4);
                float p2 = __shfl_xor_sync(0xffffffffu, v2, 4);
                float p3 = __shfl_xor_sync(0xffffffffu, v3, 4);
                if (!(g & 1)) {
                    unsigned h0, l0, h1, l1, h2, l2, h3, l3;
                    split2(v0, p0, h0, l0);
                    split2(v1, p1, h1, l1);
                    split2(v2, p2, h2, l2);
                    split2(v3, p3, h3, l3);
                    const size_t i0 = (size_t)(row0 >> 1) * DD + col;
                    const size_t i1 = (size_t)((row0 + 8) >> 1) * DD + col;
                    *(uint2*)&g_VkPh[i0] = make_uint2(h0, h1);
                    *(uint2*)&g_VkPl[i0] = make_uint2(l0, l1);
                    *(uint2*)&g_VkPh[i1] = make_uint2(h2, h3);
                    *(uint2*)&g_VkPl[i1] = make_uint2(l2, l3);
                }
            } else {
                unsigned h0, l0, h1, l1;
                split2(v0, v1, h0, l0);
                split2(v2, v3, h1, l1);
                const size_t i0 = (size_t)row0 * DD2 + (col >> 1);
                const size_t i1 = (size_t)(row0 + 8) * DD2 + (col >> 1);
                Yh[i0] = h0; Yl[i0] = l0;
                Yh[i1] = h1; Yl[i1] = l1;
            }
        }
    }
}

// ---------------- structural bias (Q pre-scaled) ----------------------------
__device__ __forceinline__ float sbias(float s, unsigned a, unsigned bId) {
    const unsigned x = a ^ bId, o = a | bId;
    float bias = 0.f;
    if ((x & MF)  == 0u) bias += 1.0f;
    if ((x & ME)  == 0u) bias += 1.0f;
    if ((x & MT)  == 0u) bias += 0.5f;
    if ((x & MTT) == 0u) bias += 0.3f;
    if ((x & MR)  == 0u) bias += 0.5f;
    if (o & EDNZ)        bias += 1.5f;
    const float v = s + bias;
    return (o & PADB) ? -1e30f : v;
}

// ---------------- fused attention (bf16x2 mma, K via ldmatrix) --------------
__global__ __launch_bounds__(256, 1)
void attn_bf16()
{
    __shared__ unsigned KsH[64][36], KsL[64][36];   // [key][dim-pair]
    __shared__ unsigned VsH[32][72], VsL[32][72];   // [key-pair][dim]
    __shared__ unsigned pk_s[64];

    const int t = threadIdx.x, w = t >> 5, lane = t & 31;
    const int g = lane >> 2, tig = lane & 3;
    const int qb = blockIdx.x * 128;
    const int h  = blockIdx.y, b = blockIdx.z;
    const int row_g = qb + w * 16 + g;

    const unsigned* Qh = g_Qh + (size_t)b * SS * DD2 + h * 32;
    const unsigned* Ql = g_Ql + (size_t)b * SS * DD2 + h * 32;
    const unsigned* Kh = g_Kh + (size_t)b * SS * DD2 + h * 32;
    const unsigned* Kl = g_Kl + (size_t)b * SS * DD2 + h * 32;
    const unsigned* Vh = g_VkPh + (size_t)b * (SS / 2) * DD + h * 64;
    const unsigned* Vl = g_VkPl + (size_t)b * (SS / 2) * DD + h * 64;

    // persistent Q fragments
    unsigned qh[4][4], ql[4][4];
#pragma unroll
    for (int ks = 0; ks < 4; ks++) {
        qh[ks][0] = Qh[(size_t)row_g       * DD2 + ks * 8 + tig];
        qh[ks][1] = Qh[(size_t)(row_g + 8) * DD2 + ks * 8 + tig];
        qh[ks][2] = Qh[(size_t)row_g       * DD2 + ks * 8 + 4 + tig];
        qh[ks][3] = Qh[(size_t)(row_g + 8) * DD2 + ks * 8 + 4 + tig];
        ql[ks][0] = Ql[(size_t)row_g       * DD2 + ks * 8 + tig];
        ql[ks][1] = Ql[(size_t)(row_g + 8) * DD2 + ks * 8 + tig];
        ql[ks][2] = Ql[(size_t)row_g       * DD2 + ks * 8 + 4 + tig];
        ql[ks][3] = Ql[(size_t)(row_g + 8) * DD2 + ks * 8 + 4 + tig];
    }

    // K ldmatrix base addresses
    const int rowBo = (lane & 7) + ((lane >> 4) << 3), colB = ((lane >> 3) & 1) * 4;
    unsigned kHaddr[4], kLaddr[4];
#pragma unroll
    for (int ntp = 0; ntp < 4; ntp++) {
        const int r = ntp * 16 + rowBo;
        kHaddr[ntp] = smem_u32(&KsH[0][0]) + (r * 36 + colB) * 4;
        kLaddr[ntp] = smem_u32(&KsL[0][0]) + (r * 36 + colB) * 4;
    }

    const unsigned rp0 = g_packed[b * SS + row_g];
    const unsigned rp1 = g_packed[b * SS + row_g + 8];

    float m0 = -1e30f, m1 = -1e30f, l0 = 0.f, l1 = 0.f;
    float O[8][4];
#pragma unroll
    for (int nt = 0; nt < 8; nt++)
#pragma unroll
        for (int i = 0; i < 4; i++) O[nt][i] = 0.f;

    for (int j0 = 0; j0 < SS; j0 += 64) {
        __syncthreads();
#pragma unroll
        for (int i = 0; i < 2; i++) {
            const int idx = i * 256 + t;
            const int r = idx >> 3, cp = (idx & 7) * 4;
            *(uint4*)&KsH[r][cp] = *(const uint4*)&Kh[(size_t)(j0 + r) * DD2 + cp];
            *(uint4*)&KsL[r][cp] = *(const uint4*)&Kl[(size_t)(j0 + r) * DD2 + cp];
        }
#pragma unroll
        for (int i = 0; i < 2; i++) {
            const int idx = i * 256 + t;
            const int r = idx >> 4, c = (idx & 15) * 4;
            *(uint4*)&VsH[r][c] = *(const uint4*)&Vh[(size_t)(j0 / 2 + r) * DD + c];
            *(uint4*)&VsL[r][c] = *(const uint4*)&Vl[(size_t)(j0 / 2 + r) * DD + c];
        }
        if (t < 64) pk_s[t] = g_packed[b * SS + j0 + t];
        __syncthreads();

        // S = Q K^T (K-frags via ldmatrix.x4: two n-tiles per load)
        float S[8][4];
#pragma unroll
        for (int nt = 0; nt < 8; nt++)
#pragma unroll
            for (int i = 0; i < 4; i++) S[nt][i] = 0.f;
#pragma unroll
        for (int ks = 0; ks < 4; ks++) {
            const int kb = ks * 32;
#pragma unroll
            for (int ntp = 0; ntp < 4; ntp++) {
                unsigned h0E, h1E, h0O, h1O, l0E, l1E, l0O, l1O;
                LDMX4(h0E, h1E, h0O, h1O, kHaddr[ntp] + kb);
                LDMX4(l0E, l1E, l0O, l1O, kLaddr[ntp] + kb);
                mma_bf16(S[2 * ntp],     qh[ks], h0E, h1E);
                mma_bf16(S[2 * ntp],     ql[ks], h0E, h1E);
                mma_bf16(S[2 * ntp],     qh[ks], l0E, l1E);
                mma_bf16(S[2 * ntp + 1], qh[ks], h0O, h1O);
                mma_bf16(S[2 * ntp + 1], ql[ks], h0O, h1O);
                mma_bf16(S[2 * ntp + 1], qh[ks], l0O, l1O);
            }
        }

        // bias + row max
        float mloc0 = -1e30f, mloc1 = -1e30f;
#pragma unroll
        for (int nt = 0; nt < 8; nt++) {
            const unsigned cp0 = pk_s[nt * 8 + tig * 2];
            const unsigned cp1 = pk_s[nt * 8 + tig * 2 + 1];
            S[nt][0] = sbias(S[nt][0], rp0, cp0);
            S[nt][1] = sbias(S[nt][1], rp0, cp1);
            S[nt][2] = sbias(S[nt][2], rp1, cp0);
            S[nt][3] = sbias(S[nt][3], rp1, cp1);
            mloc0 = fmaxf(mloc0, fmaxf(S[nt][0], S[nt][1]));
            mloc1 = fmaxf(mloc1, fmaxf(S[nt][2], S[nt][3]));
        }
        mloc0 = fmaxf(mloc0, __shfl_xor_sync(0xffffffffu, mloc0, 1));
        mloc0 = fmaxf(mloc0, __shfl_xor_sync(0xffffffffu, mloc0, 2));
        mloc1 = fmaxf(mloc1, __shfl_xor_sync(0xffffffffu, mloc1, 1));
        mloc1 = fmaxf(mloc1, __shfl_xor_sync(0xffffffffu, mloc1, 2));

        const float mn0 = fmaxf(m0, mloc0), mn1 = fmaxf(m1, mloc1);
        float ps0 = 0.f, ps1 = 0.f;
#pragma unroll
        for (int nt = 0; nt < 8; nt++) {
            S[nt][0] = __expf(S[nt][0] - mn0); ps0 += S[nt][0];
            S[nt][1] = __expf(S[nt][1] - mn0); ps0 += S[nt][1];
            S[nt][2] = __expf(S[nt][2] - mn1); ps1 += S[nt][2];
            S[nt][3] = __expf(S[nt][3] - mn1); ps1 += S[nt][3];
        }
        ps0 += __shfl_xor_sync(0xffffffffu, ps0, 1);
        ps0 += __shfl_xor_sync(0xffffffffu, ps0, 2);
        ps1 += __shfl_xor_sync(0xffffffffu, ps1, 1);
        ps1 += __shfl_xor_sync(0xffffffffu, ps1, 2);

        const float al0 = __expf(m0 - mn0), al1 = __expf(m1 - mn1);
        l0 = l0 * al0 + ps0;  l1 = l1 * al1 + ps1;
        m0 = mn0; m1 = mn1;
#pragma unroll
        for (int nt = 0; nt < 8; nt++) {
            O[nt][0] *= al0; O[nt][1] *= al0;
            O[nt][2] *= al1; O[nt][3] *= al1;
        }

        // PV
#pragma unroll
        for (int kk = 0; kk < 4; kk++) {
            unsigned pah[4], pal[4];
            split2(S[2 * kk    ][0], S[2 * kk    ][1], pah[0], pal[0]);
            split2(S[2 * kk    ][2], S[2 * kk    ][3], pah[1], pal[1]);
            split2(S[2 * kk + 1][0], S[2 * kk + 1][1], pah[2], pal[2]);
            split2(S[2 * kk + 1][2], S[2 * kk + 1][3], pah[3], pal[3]);
#pragma unroll
            for (int nt = 0; nt < 8; nt++) {
                const unsigned vh0 = VsH[kk * 8 + tig    ][nt * 8 + g];
                const unsigned vh1 = VsH[kk * 8 + 4 + tig][nt * 8 + g];
                const unsigned vl0 = VsL[kk * 8 + tig    ][nt * 8 + g];
                const unsigned vl1 = VsL[kk * 8 + 4 + tig][nt * 8 + g];
                mma_bf16(O[nt], pah, vh0, vh1);
                mma_bf16(O[nt], pal, vh0, vh1);
                mma_bf16(O[nt], pah, vl0, vl1);
            }
        }
    }

    // normalize + write split for the O-projection
    const float inv0 = 1.f / l0, inv1 = 1.f / l1;
    const size_t rbase0 = (size_t)(b * SS + qb + w * 16 + g) * DD2 + h * 32;
    const size_t rbase1 = rbase0 + 8 * DD2;
#pragma unroll
    for (int nt = 0; nt < 8; nt++) {
        const int cp = nt * 4 + tig;   // pair index within head
        unsigned h0, l0u, h1, l1u;
        split2(O[nt][0] * inv0, O[nt][1] * inv0, h0, l0u);
        split2(O[nt][2] * inv1, O[nt][3] * inv1, h1, l1u);
        g_AOh[rbase0 + cp] = h0; g_AOl[rbase0 + cp] = l0u;
        g_AOh[rbase1 + cp] = h1; g_AOl[rbase1 + cp] = l1u;
    }
}

// ---------------- launch ----------------------------------------------------
extern "C" void kernel_launch(void* const* d_in, const int* in_sizes, int n_in,
                              void* d_out, int out_size)
{
    (void)in_sizes; (void)n_in; (void)out_size;
    const float* query = (const float*)d_in[0];
    const float* key_  = (const float*)d_in[1];
    const float* value = (const float*)d_in[2];
    const int* fid = (const int*)d_in[3];
    const int* eid = (const int*)d_in[4];
    const int* tid = (const int*)d_in[5];
    const int* ttd = (const int*)d_in[6];
    const int* edd = (const int*)d_in[7];
    const int* rid = (const int*)d_in[8];
    const float* Wq = (const float*)d_in[9];
    const float* bq = (const float*)d_in[10];
    const float* Wk = (const float*)d_in[11];
    const float* bk = (const float*)d_in[12];
    const float* Wv = (const float*)d_in[13];
    const float* bv = (const float*)d_in[14];
    const float* Wo = (const float*)d_in[15];
    const float* bo = (const float*)d_in[16];
    float* out = (float*)d_out;

    const int NPX = MTOT * DD2;   // input pairs per tensor
    const int NPW = DD * DD2;     // weight pairs per matrix
    const int TB = 256;

    split_src_kernel<<<(NPX + TB - 1) / TB, TB>>>(query, 0, (size_t)0 * NPX, NPX);
    split_src_kernel<<<(NPX + TB - 1) / TB, TB>>>(key_,  0, (size_t)1 * NPX, NPX);
    split_src_kernel<<<(NPX + TB - 1) / TB, TB>>>(value, 0, (size_t)2 * NPX, NPX);
    split_src_kernel<<<(NPW + TB - 1) / TB, TB>>>(Wq, 1, (size_t)0 * NPW, NPW);
    split_src_kernel<<<(NPW + TB - 1) / TB, TB>>>(Wk, 1, (size_t)1 * NPW, NPW);
    split_src_kernel<<<(NPW + TB - 1) / TB, TB>>>(Wv, 1, (size_t)2 * NPW, NPW);
    split_src_kernel<<<(NPW + TB - 1) / TB, TB>>>(Wo, 1, (size_t)3 * NPW, NPW);

    pack_ids_kernel<<<(MTOT + TB - 1) / TB, TB>>>(fid, eid, tid, ttd, edd, rid, MTOT);

    gemm_pre<<<dim3(DD / 128, MTOT / 128, 3), 256>>>(bq, bk, bv, nullptr, 0);

    attn_bf16<<<dim3(SS / 128, HH, BB), 256>>>();

    gemm_pre<<<dim3(DD / 128, MTOT / 128, 1), 256>>>(bo, nullptr, nullptr, out, 1);
}